// round 2
// baseline (speedup 1.0000x reference)
#include <cuda_runtime.h>
#include <cstdint>

#define NTOK_MAX 8192
#define DM 1024
#define DFF 4096
#define NE 8
#define TOPK 2
#define MAX_SLOTS (2*NTOK_MAX + NE*128)   /* 17408: every expert segment padded to 128 */

// ---------------- scratch (static device memory; no allocation) ----------------
__device__ float g_xr[(size_t)NTOK_MAX*DM];          // x rounded to tf32
__device__ float g_h[(size_t)MAX_SLOTS*DFF];         // hidden activations (tf32-rounded)
__device__ float g_contrib[(size_t)MAX_SLOTS*DM];    // per-slot weighted expert outputs
__device__ int   g_perm[MAX_SLOTS];                  // slot -> token (-1 = pad)
__device__ float g_wslot[MAX_SLOTS];                 // slot -> combine weight
__device__ int   g_topi[NTOK_MAX*TOPK];
__device__ float g_topw[NTOK_MAX*TOPK];
__device__ int   g_slotof[NTOK_MAX*TOPK];            // (token,k) -> slot
__device__ int   g_counts[NE];
__device__ float g_sumprob[NE];
__device__ int   g_offs[NE+1];                       // padded exclusive scan
__device__ int   g_cursor[NE];
__device__ int   g_mtiles;                           // active 128-row m tiles

// ---------------- helpers ----------------
__device__ __forceinline__ float tf32r(float x) {
    uint32_t u;
    asm("cvt.rna.tf32.f32 %0, %1;\n" : "=r"(u) : "f"(x));
    return __uint_as_float(u);
}
__device__ __forceinline__ uint32_t tf32u(float x) {
    uint32_t u;
    asm("cvt.rna.tf32.f32 %0, %1;\n" : "=r"(u) : "f"(x));
    return u;
}
__device__ __forceinline__ float gelu_exact(float v) {
    return 0.5f * v * (1.0f + erff(v * 0.70710678118654752440f));
}
__device__ __forceinline__ void cp16(void* smem_dst, const void* gsrc, int sz) {
    uint32_t sa = (uint32_t)__cvta_generic_to_shared(smem_dst);
    asm volatile("cp.async.cg.shared.global [%0], [%1], 16, %2;\n"
                 :: "r"(sa), "l"(gsrc), "r"(sz) : "memory");
}
__device__ __forceinline__ void cp_commit() { asm volatile("cp.async.commit_group;\n" ::: "memory"); }
__device__ __forceinline__ void cp_wait1()  { asm volatile("cp.async.wait_group 1;\n" ::: "memory"); }

__device__ __forceinline__ void mma8(float* c, const uint32_t* a, const uint32_t* b) {
    asm volatile(
        "mma.sync.aligned.m16n8k8.row.col.f32.tf32.tf32.f32 "
        "{%0,%1,%2,%3},{%4,%5,%6,%7},{%8,%9},{%0,%1,%2,%3};\n"
        : "+f"(c[0]), "+f"(c[1]), "+f"(c[2]), "+f"(c[3])
        : "r"(a[0]), "r"(a[1]), "r"(a[2]), "r"(a[3]), "r"(b[0]), "r"(b[1]));
}

// ---------------- small kernels ----------------
__global__ void init_kernel() {
    int i = blockIdx.x * blockDim.x + threadIdx.x;
    if (i < MAX_SLOTS) g_perm[i] = -1;
    if (i < NE) { g_counts[i] = 0; g_sumprob[i] = 0.0f; }
}

__global__ void gating_kernel(const float* __restrict__ x, const float* __restrict__ Wg, int ntok) {
    int warp = threadIdx.x >> 5, lane = threadIdx.x & 31;
    int t = blockIdx.x * 8 + warp;
    if (t >= ntok) return;
    const float* xrow = x + (size_t)t * DM;
    float p[NE];
#pragma unroll
    for (int e = 0; e < NE; e++) p[e] = 0.0f;
#pragma unroll 4
    for (int i = 0; i < DM / 32; i++) {
        int k = i * 32 + lane;
        float xv = xrow[k];
        g_xr[(size_t)t * DM + k] = tf32r(xv);
        const float4* wrow = (const float4*)(Wg + (size_t)k * NE);
        float4 wa = wrow[0], wb = wrow[1];
        p[0] = fmaf(xv, wa.x, p[0]); p[1] = fmaf(xv, wa.y, p[1]);
        p[2] = fmaf(xv, wa.z, p[2]); p[3] = fmaf(xv, wa.w, p[3]);
        p[4] = fmaf(xv, wb.x, p[4]); p[5] = fmaf(xv, wb.y, p[5]);
        p[6] = fmaf(xv, wb.z, p[6]); p[7] = fmaf(xv, wb.w, p[7]);
    }
#pragma unroll
    for (int e = 0; e < NE; e++)
#pragma unroll
        for (int off = 16; off > 0; off >>= 1)
            p[e] += __shfl_xor_sync(0xFFFFFFFFu, p[e], off);
    if (lane == 0) {
        float mx = p[0];
#pragma unroll
        for (int e = 1; e < NE; e++) mx = fmaxf(mx, p[e]);
        float s = 0.0f, pr[NE];
#pragma unroll
        for (int e = 0; e < NE; e++) { pr[e] = expf(p[e] - mx); s += pr[e]; }
        float inv_s = 1.0f / s;
#pragma unroll
        for (int e = 0; e < NE; e++) pr[e] *= inv_s;
        int i1 = 0;
#pragma unroll
        for (int e = 1; e < NE; e++) if (pr[e] > pr[i1]) i1 = e;
        int i2 = (i1 == 0) ? 1 : 0;
#pragma unroll
        for (int e = 0; e < NE; e++) if (e != i1 && pr[e] > pr[i2]) i2 = e;
        float v1 = pr[i1], v2 = pr[i2];
        float winv = 1.0f / (v1 + v2 + 1e-9f);
        g_topi[2 * t]     = i1; g_topw[2 * t]     = v1 * winv;
        g_topi[2 * t + 1] = i2; g_topw[2 * t + 1] = v2 * winv;
        atomicAdd(&g_counts[i1], 1);
        atomicAdd(&g_counts[i2], 1);
#pragma unroll
        for (int e = 0; e < NE; e++) atomicAdd(&g_sumprob[e], pr[e]);
    }
}

__global__ void offsets_kernel(float* __restrict__ out, int has_aux, int ntok) {
    if (threadIdx.x != 0 || blockIdx.x != 0) return;
    int off = 0;
    for (int e = 0; e < NE; e++) {
        g_offs[e] = off;
        off += (g_counts[e] + 127) & ~127;
        g_cursor[e] = 0;
    }
    g_offs[NE] = off;
    g_mtiles = off >> 7;
    if (has_aux) {
        float aux = 0.0f;
        for (int e = 0; e < NE; e++) aux += (float)g_counts[e] * g_sumprob[e];
        aux *= (float)NE / ((float)ntok * (float)ntok);
        out[(size_t)ntok * DM] = aux;
    }
}

__global__ void scatter_kernel(int ntok) {
    int t = blockIdx.x * blockDim.x + threadIdx.x;
    if (t >= ntok) return;
#pragma unroll
    for (int k = 0; k < TOPK; k++) {
        int e = g_topi[2 * t + k];
        int pos = atomicAdd(&g_cursor[e], 1);
        int slot = g_offs[e] + pos;
        g_perm[slot] = t;
        g_wslot[slot] = g_topw[2 * t + k];
        g_slotof[2 * t + k] = slot;
    }
}

// -------- tiled tf32 mma GEMM, 128(m) x 256(n) x 16(k), 512 threads, 3-stage cp.async.
// PHASE 1: gathered x @ W1 (+bias, gelu) -> h ; PHASE 2: h @ W2 (+bias) * w -> contrib.
// B (weights) is read raw fp32 and rounded to tf32 (RNA) at fragment-load time.
#define SAS 20    /* A smem row stride (floats): conflict-free frag loads */
#define SBS 264   /* B smem row stride (floats): conflict-free frag loads */
#define SMEM_FLOATS (3*128*SAS + 3*16*SBS + 128 + 128)

template<int PHASE>
__global__ void __launch_bounds__(512, 1) moe_gemm(const float* __restrict__ W,
                                                   const float* __restrict__ bias) {
    constexpr int K   = (PHASE == 1) ? DM : DFF;
    constexpr int LDB = (PHASE == 1) ? DFF : DM;
    constexpr int NB  = (PHASE == 1) ? DFF : DM;   // bias length per expert
    constexpr int KT  = K / 16;

    int mt = blockIdx.y;
    if (mt >= g_mtiles) return;
    int m0 = mt * 128;
    int n0 = blockIdx.x * 256;

    // expert of this m tile (segments are 128-aligned)
    int e = 0;
#pragma unroll
    for (int i = 0; i < NE; i++) if (m0 >= g_offs[i + 1]) e = i + 1;

    const float* Bp = W + (size_t)e * DM * DFF + n0;
    const float* biasE = bias + (size_t)e * NB;

    extern __shared__ float smem[];
    float* sAbase = smem;                       // 3 * 128*SAS
    float* sBbase = sAbase + 3 * 128 * SAS;     // 3 * 16*SBS
    int*   s_tok  = (int*)(sBbase + 3 * 16 * SBS);
    float* s_w    = (float*)(s_tok + 128);

    int tid = threadIdx.x;
    if (tid < 128) {
        s_tok[tid] = g_perm[m0 + tid];
        s_w[tid]   = g_wslot[m0 + tid];
    }
    __syncthreads();

    auto prefetch = [&](int buf, int kt) {
        {   // A: 128 rows x 16 floats = 512 x 16B chunks, one per thread
            int row = tid >> 2, seg = tid & 3;
            const float* src;
            int sz = 16;
            if (PHASE == 1) {
                int tok = s_tok[row];
                if (tok < 0) { sz = 0; src = g_xr; }
                else src = g_xr + (size_t)tok * DM + kt * 16 + seg * 4;
            } else {
                src = g_h + (size_t)(m0 + row) * DFF + kt * 16 + seg * 4;
            }
            cp16(&sAbase[buf * 128 * SAS + row * SAS + seg * 4], src, sz);
        }
#pragma unroll
        for (int rep = 0; rep < 2; rep++) {     // B: 16 rows x 256 floats = 1024 x 16B chunks
            int c = tid + rep * 512;
            int k = c >> 6, seg = c & 63;
            const float* src = Bp + (size_t)(kt * 16 + k) * LDB + seg * 4;
            cp16(&sBbase[buf * 16 * SBS + k * SBS + seg * 4], src, 16);
        }
    };

    int warp = tid >> 5, lane = tid & 31;
    int warp_m = (warp >> 2) * 32;   // 4 warps in m (32 rows each)
    int warp_n = (warp & 3) * 64;    // 4 warps in n (64 cols each)
    int g = lane >> 2, tg = lane & 3;

    float acc[2][8][4];
#pragma unroll
    for (int a = 0; a < 2; a++)
#pragma unroll
        for (int b = 0; b < 8; b++)
#pragma unroll
            for (int c = 0; c < 4; c++) acc[a][b][c] = 0.0f;

    prefetch(0, 0); cp_commit();
    prefetch(1, 1); cp_commit();

    for (int kt = 0; kt < KT; kt++) {
        int cur = kt % 3;
        cp_wait1();
        __syncthreads();
        if (kt + 2 < KT) prefetch((kt + 2) % 3, kt + 2);
        cp_commit();    // always commit (possibly empty group) to keep count math simple

        const float* A = sAbase + cur * 128 * SAS;
        const float* B = sBbase + cur * 16 * SBS;
#pragma unroll
        for (int ks = 0; ks < 2; ks++) {
            int kb = ks * 8;
            uint32_t af[2][4], bf[8][2];
#pragma unroll
            for (int mi = 0; mi < 2; mi++) {
                int r0 = warp_m + mi * 16 + g;
                af[mi][0] = __float_as_uint(A[(r0)     * SAS + kb + tg]);
                af[mi][1] = __float_as_uint(A[(r0 + 8) * SAS + kb + tg]);
                af[mi][2] = __float_as_uint(A[(r0)     * SAS + kb + tg + 4]);
                af[mi][3] = __float_as_uint(A[(r0 + 8) * SAS + kb + tg + 4]);
            }
#pragma unroll
            for (int ni = 0; ni < 8; ni++) {
                int col = warp_n + ni * 8 + g;
                bf[ni][0] = tf32u(B[(kb + tg)     * SBS + col]);
                bf[ni][1] = tf32u(B[(kb + tg + 4) * SBS + col]);
            }
#pragma unroll
            for (int mi = 0; mi < 2; mi++)
#pragma unroll
                for (int ni = 0; ni < 8; ni++)
                    mma8(acc[mi][ni], af[mi], bf[ni]);
        }
        __syncthreads();
    }

    // epilogue
#pragma unroll
    for (int mi = 0; mi < 2; mi++) {
#pragma unroll
        for (int r2 = 0; r2 < 2; r2++) {
            int row = warp_m + mi * 16 + g + r2 * 8;
            int gm = m0 + row;
            int tok = s_tok[row];
            float w = s_w[row];
            if (PHASE == 2 && tok < 0) continue;
#pragma unroll
            for (int ni = 0; ni < 8; ni++) {
                int col = warp_n + ni * 8 + tg * 2;
                int gn = n0 + col;
                float v0 = acc[mi][ni][r2 * 2 + 0] + biasE[gn];
                float v1 = acc[mi][ni][r2 * 2 + 1] + biasE[gn + 1];
                if (PHASE == 1) {
                    float2 o;
                    o.x = tf32r(gelu_exact(v0));
                    o.y = tf32r(gelu_exact(v1));
                    *(float2*)&g_h[(size_t)gm * DFF + gn] = o;
                } else {
                    float2 o;
                    o.x = w * v0;
                    o.y = w * v1;
                    *(float2*)&g_contrib[(size_t)gm * DM + gn] = o;
                }
            }
        }
    }
}

__global__ void combine_kernel(float* __restrict__ out) {
    int t = blockIdx.x, c = threadIdx.x;   // 256 threads x float4 = 1024 floats
    int s0 = g_slotof[2 * t], s1 = g_slotof[2 * t + 1];
    const float4* r0 = (const float4*)(g_contrib + (size_t)s0 * DM);
    const float4* r1 = (const float4*)(g_contrib + (size_t)s1 * DM);
    float4 a = r0[c], b = r1[c];
    float4 o;
    o.x = a.x + b.x; o.y = a.y + b.y; o.z = a.z + b.z; o.w = a.w + b.w;
    ((float4*)out)[(size_t)t * (DM / 4) + c] = o;
}

// ---------------- launch ----------------
extern "C" void kernel_launch(void* const* d_in, const int* in_sizes, int n_in,
                              void* d_out, int out_size) {
    const float* x  = (const float*)d_in[0];
    const float* Wg = (const float*)d_in[1];
    const float* W1 = (const float*)d_in[2];
    const float* b1 = (const float*)d_in[3];
    const float* W2 = (const float*)d_in[4];
    const float* b2 = (const float*)d_in[5];
    float* out = (float*)d_out;

    int ntok = in_sizes[0] / DM;                 // 8192 for the reference shapes
    int has_aux = (out_size > ntok * DM) ? 1 : 0;
    int max_mtiles = (2 * ntok + NE * 127 + 127) / 128;

    const int smem_bytes = SMEM_FLOATS * 4;      // ~82.4 KB -> needs opt-in
    cudaFuncSetAttribute(moe_gemm<1>, cudaFuncAttributeMaxDynamicSharedMemorySize, smem_bytes);
    cudaFuncSetAttribute(moe_gemm<2>, cudaFuncAttributeMaxDynamicSharedMemorySize, smem_bytes);

    init_kernel<<<(MAX_SLOTS + 255) / 256, 256>>>();
    gating_kernel<<<(ntok + 7) / 8, 256>>>(x, Wg, ntok);
    offsets_kernel<<<1, 32>>>(out, has_aux, ntok);
    scatter_kernel<<<(ntok + 255) / 256, 256>>>(ntok);
    moe_gemm<1><<<dim3(DFF / 256, max_mtiles), 512, smem_bytes>>>(W1, b1);
    moe_gemm<2><<<dim3(DM / 256, max_mtiles), 512, smem_bytes>>>(W2, b2);
    combine_kernel<<<ntok, 256>>>(out);
}

// round 9
// speedup vs baseline: 1.3125x; 1.3125x over previous
#include <cuda_runtime.h>
#include <cuda_fp16.h>
#include <cstdint>

#define NTOK_MAX 8192
#define DM 1024
#define DFF 4096
#define NE 8
#define TOPK 2
#define MAX_SLOTS (2*NTOK_MAX + NE*128)   /* 17408: every expert segment padded to 128 */

// ---------------- scratch (static device memory; no allocation) ----------------
__device__ __half g_xh[(size_t)NTOK_MAX*DM];         // x rounded to fp16
__device__ __half g_hh[(size_t)MAX_SLOTS*DFF];       // hidden activations (fp16)
__device__ float  g_contrib[(size_t)MAX_SLOTS*DM];   // per-slot weighted expert outputs
__device__ int    g_perm[MAX_SLOTS];                 // slot -> token (-1 = pad)
__device__ float  g_wslot[MAX_SLOTS];                // slot -> combine weight
__device__ int    g_topi[NTOK_MAX*TOPK];
__device__ float  g_topw[NTOK_MAX*TOPK];
__device__ int    g_slotof[NTOK_MAX*TOPK];           // (token,k) -> slot
__device__ int    g_counts[NE];
__device__ float  g_sumprob[NE];
__device__ int    g_offs[NE+1];                      // padded exclusive scan
__device__ int    g_cursor[NE];
__device__ int    g_mtiles;                          // active 128-row m tiles

// ---------------- helpers ----------------
__device__ __forceinline__ float gelu_exact(float v) {
    return 0.5f * v * (1.0f + erff(v * 0.70710678118654752440f));
}
__device__ __forceinline__ void cp16(void* smem_dst, const void* gsrc, int sz) {
    uint32_t sa = (uint32_t)__cvta_generic_to_shared(smem_dst);
    asm volatile("cp.async.cg.shared.global [%0], [%1], 16, %2;\n"
                 :: "r"(sa), "l"(gsrc), "r"(sz) : "memory");
}
__device__ __forceinline__ void cp_commit() { asm volatile("cp.async.commit_group;\n" ::: "memory"); }
__device__ __forceinline__ void cp_wait1()  { asm volatile("cp.async.wait_group 1;\n" ::: "memory"); }

// fp16 tensor-core mma: D(16x8,f32) += A(16x16,f16) * B(16x8,f16)
__device__ __forceinline__ void mma16(float* c, const uint32_t* a, const uint32_t* b) {
    asm volatile(
        "mma.sync.aligned.m16n8k16.row.col.f32.f16.f16.f32 "
        "{%0,%1,%2,%3},{%4,%5,%6,%7},{%8,%9},{%0,%1,%2,%3};\n"
        : "+f"(c[0]), "+f"(c[1]), "+f"(c[2]), "+f"(c[3])
        : "r"(a[0]), "r"(a[1]), "r"(a[2]), "r"(a[3]), "r"(b[0]), "r"(b[1]));
}

// ---------------- small kernels ----------------
__global__ void init_kernel() {
    int i = blockIdx.x * blockDim.x + threadIdx.x;
    if (i < MAX_SLOTS) g_perm[i] = -1;
    if (i < NE) { g_counts[i] = 0; g_sumprob[i] = 0.0f; }
}

__global__ void gating_kernel(const float* __restrict__ x, const float* __restrict__ Wg, int ntok) {
    int warp = threadIdx.x >> 5, lane = threadIdx.x & 31;
    int t = blockIdx.x * 8 + warp;
    if (t >= ntok) return;
    const float* xrow = x + (size_t)t * DM;
    float p[NE];
#pragma unroll
    for (int e = 0; e < NE; e++) p[e] = 0.0f;
#pragma unroll 4
    for (int i = 0; i < DM / 32; i++) {
        int k = i * 32 + lane;
        float xv = xrow[k];
        g_xh[(size_t)t * DM + k] = __float2half_rn(xv);
        const float4* wrow = (const float4*)(Wg + (size_t)k * NE);
        float4 wa = wrow[0], wb = wrow[1];
        p[0] = fmaf(xv, wa.x, p[0]); p[1] = fmaf(xv, wa.y, p[1]);
        p[2] = fmaf(xv, wa.z, p[2]); p[3] = fmaf(xv, wa.w, p[3]);
        p[4] = fmaf(xv, wb.x, p[4]); p[5] = fmaf(xv, wb.y, p[5]);
        p[6] = fmaf(xv, wb.z, p[6]); p[7] = fmaf(xv, wb.w, p[7]);
    }
#pragma unroll
    for (int e = 0; e < NE; e++)
#pragma unroll
        for (int off = 16; off > 0; off >>= 1)
            p[e] += __shfl_xor_sync(0xFFFFFFFFu, p[e], off);
    if (lane == 0) {
        float mx = p[0];
#pragma unroll
        for (int e = 1; e < NE; e++) mx = fmaxf(mx, p[e]);
        float s = 0.0f, pr[NE];
#pragma unroll
        for (int e = 0; e < NE; e++) { pr[e] = expf(p[e] - mx); s += pr[e]; }
        float inv_s = 1.0f / s;
#pragma unroll
        for (int e = 0; e < NE; e++) pr[e] *= inv_s;
        int i1 = 0;
#pragma unroll
        for (int e = 1; e < NE; e++) if (pr[e] > pr[i1]) i1 = e;
        int i2 = (i1 == 0) ? 1 : 0;
#pragma unroll
        for (int e = 0; e < NE; e++) if (e != i1 && pr[e] > pr[i2]) i2 = e;
        float v1 = pr[i1], v2 = pr[i2];
        float winv = 1.0f / (v1 + v2 + 1e-9f);
        g_topi[2 * t]     = i1; g_topw[2 * t]     = v1 * winv;
        g_topi[2 * t + 1] = i2; g_topw[2 * t + 1] = v2 * winv;
        atomicAdd(&g_counts[i1], 1);
        atomicAdd(&g_counts[i2], 1);
#pragma unroll
        for (int e = 0; e < NE; e++) atomicAdd(&g_sumprob[e], pr[e]);
    }
}

__global__ void offsets_kernel(float* __restrict__ out, int has_aux, int ntok) {
    if (threadIdx.x != 0 || blockIdx.x != 0) return;
    int off = 0;
    for (int e = 0; e < NE; e++) {
        g_offs[e] = off;
        off += (g_counts[e] + 127) & ~127;
        g_cursor[e] = 0;
    }
    g_offs[NE] = off;
    g_mtiles = off >> 7;
    if (has_aux) {
        float aux = 0.0f;
        for (int e = 0; e < NE; e++) aux += (float)g_counts[e] * g_sumprob[e];
        aux *= (float)NE / ((float)ntok * (float)ntok);
        out[(size_t)ntok * DM] = aux;
    }
}

__global__ void scatter_kernel(int ntok) {
    int t = blockIdx.x * blockDim.x + threadIdx.x;
    if (t >= ntok) return;
#pragma unroll
    for (int k = 0; k < TOPK; k++) {
        int e = g_topi[2 * t + k];
        int pos = atomicAdd(&g_cursor[e], 1);
        int slot = g_offs[e] + pos;
        g_perm[slot] = t;
        g_wslot[slot] = g_topw[2 * t + k];
        g_slotof[2 * t + k] = slot;
    }
}

// -------- fp16 tensor GEMM, 128(m) x 256(n) x 16(k) per stage, 512 threads, 3-stage cp.async.
// Warp tile 64(m) x 32(n): 2 warps in m, 8 in n -> 16 A-LDS + 16 B-LDS + 8 cvt + 16 MMA per
// warp per k-tile (LDS time ~= tensor time, balanced).
// PHASE 1: gathered fp16 x @ W1 (+bias, gelu) -> fp16 h ; PHASE 2: fp16 h @ W2 (+bias)*w -> contrib.
// A in smem as fp16 (row stride 12 half2 = 48 B: frag loads conflict-free).
// B (weights) read raw fp32 (row stride 260 floats: conflict-free), cvt to half2 at frag load.
#define SAH 12    /* A smem row stride in half2 units */
#define SBS 260   /* B smem row stride in floats */
#define SMEM_BYTES (3*128*SAH*4 + 3*16*SBS*4 + 512 + 512)

template<int PHASE>
__global__ void __launch_bounds__(512, 1) moe_gemm(const float* __restrict__ W,
                                                   const float* __restrict__ bias) {
    constexpr int K   = (PHASE == 1) ? DM : DFF;
    constexpr int LDB = (PHASE == 1) ? DFF : DM;
    constexpr int NB  = (PHASE == 1) ? DFF : DM;   // bias length per expert
    constexpr int KT  = K / 16;

    int mt = blockIdx.y;
    if (mt >= g_mtiles) return;
    int m0 = mt * 128;
    int n0 = blockIdx.x * 256;

    // expert of this m tile (segments are 128-aligned)
    int e = 0;
#pragma unroll
    for (int i = 0; i < NE; i++) if (m0 >= g_offs[i + 1]) e = i + 1;

    const float* Bp    = W + (size_t)e * DM * DFF + n0;
    const float* biasE = bias + (size_t)e * NB;

    extern __shared__ char smem[];
    __half2* sAbase = (__half2*)smem;                     // 3 * 128*SAH half2
    float*   sBbase = (float*)(smem + 3 * 128 * SAH * 4); // 3 * 16*SBS floats
    int*     s_tok  = (int*)(sBbase + 3 * 16 * SBS);
    float*   s_w    = (float*)(s_tok + 128);

    int tid = threadIdx.x;
    if (tid < 128) {
        s_tok[tid] = g_perm[m0 + tid];
        s_w[tid]   = g_wslot[m0 + tid];
    }
    __syncthreads();

    // precomputed per-thread fill pointers/addresses
    int aRow = tid >> 1, aSeg = tid & 1;
    const __half* aSrcBase;
    int aSz = 16;
    if (PHASE == 1) {
        int tok = (tid < 256) ? s_tok[aRow] : -1;
        if (tok < 0) { aSz = 0; aSrcBase = g_xh; }
        else aSrcBase = g_xh + (size_t)tok * DM + aSeg * 8;
    } else {
        aSrcBase = g_hh + (size_t)(m0 + aRow) * DFF + aSeg * 8;
    }
    char* aDstBase = (char*)sAbase + aRow * (SAH * 4) + aSeg * 16;

    int bK0 = tid >> 6, bSeg0 = tid & 63;
    int bK1 = (tid + 512) >> 6, bSeg1 = (tid + 512) & 63;
    const float* bSrc0 = Bp + (size_t)bK0 * LDB + bSeg0 * 4;
    const float* bSrc1 = Bp + (size_t)bK1 * LDB + bSeg1 * 4;
    float* bDst0 = sBbase + bK0 * SBS + bSeg0 * 4;
    float* bDst1 = sBbase + bK1 * SBS + bSeg1 * 4;

    auto prefetch = [&](int buf, int kt) {
        if (tid < 256)
            cp16(aDstBase + buf * 128 * SAH * 4, aSrcBase + kt * 16, aSz);
        cp16(bDst0 + buf * 16 * SBS, bSrc0 + (size_t)kt * 16 * LDB, 16);
        cp16(bDst1 + buf * 16 * SBS, bSrc1 + (size_t)kt * 16 * LDB, 16);
    };

    int warp = tid >> 5, lane = tid & 31;
    int warp_m = (warp >> 3) * 64;   // 2 warps in m (64 rows each)
    int warp_n = (warp & 7) * 32;    // 8 warps in n (32 cols each)
    int g = lane >> 2, tg = lane & 3;

    float acc[4][4][4];
#pragma unroll
    for (int a = 0; a < 4; a++)
#pragma unroll
        for (int b = 0; b < 4; b++)
#pragma unroll
            for (int c = 0; c < 4; c++) acc[a][b][c] = 0.0f;

    prefetch(0, 0); cp_commit();
    prefetch(1, 1); cp_commit();

    for (int kt = 0; kt < KT; kt++) {
        int cur = kt % 3;
        cp_wait1();
        __syncthreads();
        if (kt + 2 < KT) prefetch((kt + 2) % 3, kt + 2);
        cp_commit();    // unconditional (possibly empty) to keep wait_group accounting fixed

        const __half2* A = sAbase + cur * 128 * SAH;
        const float*   B = sBbase + cur * 16 * SBS;

        uint32_t af[4][4], bf[4][2];
#pragma unroll
        for (int mi = 0; mi < 4; mi++) {
            int r0 = warp_m + mi * 16 + g;
            af[mi][0] = *(const uint32_t*)&A[(r0)     * SAH + tg];
            af[mi][1] = *(const uint32_t*)&A[(r0 + 8) * SAH + tg];
            af[mi][2] = *(const uint32_t*)&A[(r0)     * SAH + tg + 4];
            af[mi][3] = *(const uint32_t*)&A[(r0 + 8) * SAH + tg + 4];
        }
#pragma unroll
        for (int ni = 0; ni < 4; ni++) {
            int col = warp_n + ni * 8 + g;
            __half2 b0 = __floats2half2_rn(B[(2 * tg)     * SBS + col], B[(2 * tg + 1) * SBS + col]);
            __half2 b1 = __floats2half2_rn(B[(2 * tg + 8) * SBS + col], B[(2 * tg + 9) * SBS + col]);
            bf[ni][0] = *(uint32_t*)&b0;
            bf[ni][1] = *(uint32_t*)&b1;
        }
#pragma unroll
        for (int mi = 0; mi < 4; mi++)
#pragma unroll
            for (int ni = 0; ni < 4; ni++)
                mma16(acc[mi][ni], af[mi], bf[ni]);
        __syncthreads();
    }

    // epilogue
#pragma unroll
    for (int mi = 0; mi < 4; mi++) {
#pragma unroll
        for (int r2 = 0; r2 < 2; r2++) {
            int row = warp_m + mi * 16 + g + r2 * 8;
            int gm = m0 + row;
            int tok = s_tok[row];
            float w = s_w[row];
            if (PHASE == 2 && tok < 0) continue;
#pragma unroll
            for (int ni = 0; ni < 4; ni++) {
                int col = warp_n + ni * 8 + tg * 2;
                int gn = n0 + col;
                float v0 = acc[mi][ni][r2 * 2 + 0] + biasE[gn];
                float v1 = acc[mi][ni][r2 * 2 + 1] + biasE[gn + 1];
                if (PHASE == 1) {
                    __half2 o = __floats2half2_rn(gelu_exact(v0), gelu_exact(v1));
                    *(__half2*)&g_hh[(size_t)gm * DFF + gn] = o;
                } else {
                    float2 o;
                    o.x = w * v0;
                    o.y = w * v1;
                    *(float2*)&g_contrib[(size_t)gm * DM + gn] = o;
                }
            }
        }
    }
}

__global__ void combine_kernel(float* __restrict__ out) {
    int t = blockIdx.x, c = threadIdx.x;   // 256 threads x float4 = 1024 floats
    int s0 = g_slotof[2 * t], s1 = g_slotof[2 * t + 1];
    const float4* r0 = (const float4*)(g_contrib + (size_t)s0 * DM);
    const float4* r1 = (const float4*)(g_contrib + (size_t)s1 * DM);
    float4 a = r0[c], b = r1[c];
    float4 o;
    o.x = a.x + b.x; o.y = a.y + b.y; o.z = a.z + b.z; o.w = a.w + b.w;
    ((float4*)out)[(size_t)t * (DM / 4) + c] = o;
}

// ---------------- launch ----------------
extern "C" void kernel_launch(void* const* d_in, const int* in_sizes, int n_in,
                              void* d_out, int out_size) {
    const float* x  = (const float*)d_in[0];
    const float* Wg = (const float*)d_in[1];
    const float* W1 = (const float*)d_in[2];
    const float* b1 = (const float*)d_in[3];
    const float* W2 = (const float*)d_in[4];
    const float* b2 = (const float*)d_in[5];
    float* out = (float*)d_out;

    int ntok = in_sizes[0] / DM;                 // 8192 for the reference shapes
    int has_aux = (out_size > ntok * DM) ? 1 : 0;
    int max_mtiles = (2 * ntok + NE * 127 + 127) / 128;

    cudaFuncSetAttribute(moe_gemm<1>, cudaFuncAttributeMaxDynamicSharedMemorySize, SMEM_BYTES);
    cudaFuncSetAttribute(moe_gemm<2>, cudaFuncAttributeMaxDynamicSharedMemorySize, SMEM_BYTES);

    init_kernel<<<(MAX_SLOTS + 255) / 256, 256>>>();
    gating_kernel<<<(ntok + 7) / 8, 256>>>(x, Wg, ntok);
    offsets_kernel<<<1, 32>>>(out, has_aux, ntok);
    scatter_kernel<<<(ntok + 255) / 256, 256>>>(ntok);
    moe_gemm<1><<<dim3(DFF / 256, max_mtiles), 512, SMEM_BYTES>>>(W1, b1);
    moe_gemm<2><<<dim3(DM / 256, max_mtiles), 512, SMEM_BYTES>>>(W2, b2);
    combine_kernel<<<ntok, 256>>>(out);
}